// round 5
// baseline (speedup 1.0000x reference)
#include <cuda_runtime.h>
#include <math.h>
#include <cstdint>

#define SEQL   2048
#define NHEAD  8
#define DMODEL 512
#define HDIM   64
#define CATD   128
#define NHTOT  16

// Scratch (allocation-free). Values stored pre-rounded to tf32 bit patterns.
__device__ float g_A [(size_t)NHTOT * SEQL * CATD];   // [nh][l][c]   A operand (K-major)
__device__ float g_B [(size_t)NHTOT * SEQL * CATD];   // [nh][l][c]   B operand (K-major)
__device__ float g_Vt[(size_t)NHTOT * HDIM * SEQL];   // [nh][d][l]   stage-2 B operand (K-major)

#define DINL __device__ __forceinline__

DINL uint32_t f2tf(float f) {           // round fp32 -> tf32 (rna), fp32 bit layout
    uint32_t u;
    asm("cvt.rna.tf32.f32 %0, %1;" : "=r"(u) : "f"(f));
    return u;
}

// m16n8k8 tf32 MMA, fp32 accumulate (legacy mma.sync path, base sm_103 ISA)
DINL void mma8(float* d, const uint32_t* a, const uint32_t* b) {
    asm volatile("mma.sync.aligned.m16n8k8.row.col.f32.tf32.tf32.f32 "
        "{%0,%1,%2,%3}, {%4,%5,%6,%7}, {%8,%9}, {%0,%1,%2,%3};"
        : "+f"(d[0]), "+f"(d[1]), "+f"(d[2]), "+f"(d[3])
        : "r"(a[0]), "r"(a[1]), "r"(a[2]), "r"(a[3]), "r"(b[0]), "r"(b[1]));
}

DINL float softplus_f(float x) {
    return fmaxf(x, 0.f) + log1pf(__expf(-fabsf(x)));
}
DINL void sincos_red(float ang, float* s, float* c) {
    const float INV2PI = 0.15915494309189535f;
    const float PI2_HI = 6.28318548202514648f;
    const float PI2_LO = -1.74845553e-7f;
    float k = rintf(ang * INV2PI);
    float r = fmaf(-k, PI2_HI, ang);
    r = fmaf(-k, PI2_LO, r);
    *s = __sinf(r);
    *c = __cosf(r);
}

// ─────────────────────────── Projection GEMM (tf32 mma.sync) ────────────────
// C(128x128) = X_tile · W_tile^T over K=512 in 8 slabs of 64 (69.6KB smem -> 2 CTAs/SM).
// 8 warps: 4(M) x 2(N), warp tile 32x64.
#define PJ_PITCH 68
#define PJ_SMEM  (2 * 128 * PJ_PITCH * 4)

__global__ __launch_bounds__(256, 2) void proj_tc(
    const float* __restrict__ query, const float* __restrict__ key,
    const float* __restrict__ Wq, const float* __restrict__ Wk, const float* __restrict__ Wv,
    const float* __restrict__ coeff, const float* __restrict__ pw, const float* __restrict__ pb)
{
    extern __shared__ float sm[];
    float (*Xs)[PJ_PITCH] = (float(*)[PJ_PITCH])sm;
    float (*Ws)[PJ_PITCH] = (float(*)[PJ_PITCH])(sm + 128 * PJ_PITCH);

    int tid = threadIdx.x, wid = tid >> 5, lane = tid & 31;
    int warpM = wid >> 1, warpN = wid & 1;
    int g = lane >> 2, t = lane & 3;
    int mode = blockIdx.z;
    const float* X = (mode == 0) ? query : key;
    const float* W = (mode == 0) ? Wq : (mode == 1 ? Wk : Wv);
    int m0 = blockIdx.x * 128;
    int c0 = blockIdx.y * 128;

    float acc[2][8][4];
    #pragma unroll
    for (int mb = 0; mb < 2; ++mb)
        #pragma unroll
        for (int nb = 0; nb < 8; ++nb)
            #pragma unroll
            for (int r = 0; r < 4; ++r) acc[mb][nb][r] = 0.f;

    for (int kc = 0; kc < 8; ++kc) {
        __syncthreads();
        #pragma unroll
        for (int it = 0; it < 8; ++it) {
            int idx = it * 256 + tid;
            int r = idx >> 4, c4 = (idx & 15) * 4;
            float4 vx = *(const float4*)(X + (size_t)(m0 + r) * DMODEL + kc * 64 + c4);
            Xs[r][c4 + 0] = __uint_as_float(f2tf(vx.x));
            Xs[r][c4 + 1] = __uint_as_float(f2tf(vx.y));
            Xs[r][c4 + 2] = __uint_as_float(f2tf(vx.z));
            Xs[r][c4 + 3] = __uint_as_float(f2tf(vx.w));
            float4 vw = *(const float4*)(W + (size_t)(c0 + r) * DMODEL + kc * 64 + c4);
            Ws[r][c4 + 0] = __uint_as_float(f2tf(vw.x));
            Ws[r][c4 + 1] = __uint_as_float(f2tf(vw.y));
            Ws[r][c4 + 2] = __uint_as_float(f2tf(vw.z));
            Ws[r][c4 + 3] = __uint_as_float(f2tf(vw.w));
        }
        __syncthreads();

        #pragma unroll
        for (int ks = 0; ks < 8; ++ks) {
            int k = ks * 8;
            uint32_t a[2][4];
            #pragma unroll
            for (int mb = 0; mb < 2; ++mb) {
                int r0 = warpM * 32 + mb * 16;
                a[mb][0] = __float_as_uint(Xs[r0 + g][k + t]);
                a[mb][1] = __float_as_uint(Xs[r0 + g + 8][k + t]);
                a[mb][2] = __float_as_uint(Xs[r0 + g][k + t + 4]);
                a[mb][3] = __float_as_uint(Xs[r0 + g + 8][k + t + 4]);
            }
            uint32_t b[8][2];
            #pragma unroll
            for (int nb = 0; nb < 8; ++nb) {
                int n0 = warpN * 64 + nb * 8;
                b[nb][0] = __float_as_uint(Ws[n0 + g][k + t]);
                b[nb][1] = __float_as_uint(Ws[n0 + g][k + t + 4]);
            }
            #pragma unroll
            for (int mb = 0; mb < 2; ++mb)
                #pragma unroll
                for (int nb = 0; nb < 8; ++nb)
                    mma8(acc[mb][nb], a[mb], b[nb]);
        }
    }

    // epilogue
    #pragma unroll
    for (int mb = 0; mb < 2; ++mb) {
        #pragma unroll
        for (int nb = 0; nb < 8; ++nb) {
            #pragma unroll
            for (int r = 0; r < 4; ++r) {
                int row = warpM * 32 + mb * 16 + g + (r >> 1) * 8;
                int col = warpN * 64 + nb * 8 + 2 * t + (r & 1);
                int m = m0 + row;
                int n = m >> 11, l = m & (SEQL - 1);
                int c = c0 + col;
                int h = c >> 6, dd = c & 63;
                float x = acc[mb][nb][r];
                if (mode == 2) {
                    g_Vt[((size_t)((n * NHEAD + h) * HDIM + dd)) * SEQL + l] =
                        __uint_as_float(f2tf(x));
                } else {
                    size_t base = ((size_t)(n * NHEAD + h) * SEQL + l) * CATD;
                    float w = pw[c];
                    float sn, cs;
                    if (mode == 0) {
                        float sp = softplus_f(x);
                        sincos_red((float)l * w + pb[c], &sn, &cs);
                        g_A[base + dd]      = __uint_as_float(f2tf(sp * cs));
                        g_A[base + 64 + dd] = __uint_as_float(f2tf(sp * sn));
                    } else {
                        float sp = softplus_f(x) * coeff[c];
                        sincos_red((float)l * w, &sn, &cs);
                        g_B[base + dd]      = __uint_as_float(f2tf(sp * cs));
                        g_B[base + 64 + dd] = __uint_as_float(f2tf(sp * sn));
                    }
                }
            }
        }
    }
}

// ─────────────────────────── Attention (tf32 mma.sync, causal, abs-norm) ────
// CTA = (nh, 64 q rows). Per 64-key chunk kt<=qt:
//   mma1: S(64x64) = A(64x128) · B^T   (regs)
//   epilogue: causal mask, asum += Σ|S| (regs), S -> own smem region (tf32)
//   mma2: O(64x64) += S · Vt^T
// smem 104.4KB -> 2 CTAs/SM. 8 warps: 4(M rows of 16) x 2(N cols of 32).
#define AP128 132
#define AP64  68
// float offsets
#define AT_A   0
#define AT_B   (64 * AP128)                 // 8448
#define AT_V   (2 * 64 * AP128)             // 16896
#define AT_S   (2 * 64 * AP128 + 64 * AP64) // 21248
#define AT_AS  (2 * 64 * AP128 + 2 * 64 * AP64)
#define AT_SMEM ((AT_AS + 64 * 8) * 4)      // 104448 bytes

__global__ __launch_bounds__(256, 2) void attn_tc(float* __restrict__ out)
{
    extern __shared__ float sm[];
    float (*As)[AP128] = (float(*)[AP128])(sm + AT_A);
    float (*Bs)[AP128] = (float(*)[AP128])(sm + AT_B);
    float (*Vs)[AP64]  = (float(*)[AP64])(sm + AT_V);
    float (*Ss)[AP64]  = (float(*)[AP64])(sm + AT_S);
    float (*asums)[8]  = (float(*)[8])(sm + AT_AS);

    int tid = threadIdx.x, wid = tid >> 5, lane = tid & 31;
    int warpM = wid >> 1, warpN = wid & 1;
    int g = lane >> 2, t = lane & 3;
    int r0 = warpM * 16;
    int nh = blockIdx.y;
    int n = nh >> 3, h = nh & 7;
    int qt = (int)gridDim.x - 1 - (int)blockIdx.x;   // heavy tiles first
    int q0 = qt * 64;

    const float* Ab = g_A  + (size_t)nh * SEQL * CATD;
    const float* Bb = g_B  + (size_t)nh * SEQL * CATD;
    const float* Vb = g_Vt + (size_t)nh * HDIM * SEQL;

    // A tile (already tf32-rounded): load once, 64x128
    #pragma unroll
    for (int it = 0; it < 8; ++it) {
        int idx = it * 256 + tid;
        int r = idx >> 5, c4 = (idx & 31) * 4;
        *(float4*)&As[r][c4] = *(const float4*)(Ab + (size_t)(q0 + r) * CATD + c4);
    }

    float O[4][4];
    #pragma unroll
    for (int nb = 0; nb < 4; ++nb)
        #pragma unroll
        for (int r = 0; r < 4; ++r) O[nb][r] = 0.f;
    float asum[2] = {0.f, 0.f};

    for (int kt = 0; kt <= qt; ++kt) {
        int k0 = kt * 64;
        __syncthreads();    // prev mma1/mma2 done reading Bs/Vs (and As stores on iter 0)
        #pragma unroll
        for (int it = 0; it < 8; ++it) {
            int idx = it * 256 + tid;
            int r = idx >> 5, c4 = (idx & 31) * 4;
            *(float4*)&Bs[r][c4] = *(const float4*)(Bb + (size_t)(k0 + r) * CATD + c4);
        }
        #pragma unroll
        for (int it = 0; it < 4; ++it) {
            int idx = it * 256 + tid;
            int r = idx >> 4, c4 = (idx & 15) * 4;
            *(float4*)&Vs[r][c4] = *(const float4*)(Vb + (size_t)r * SEQL + k0 + c4);
        }
        __syncthreads();

        // mma1: S(16x32 per warp) = A · B^T over catd=128
        float S[4][4];
        #pragma unroll
        for (int nb = 0; nb < 4; ++nb)
            #pragma unroll
            for (int r = 0; r < 4; ++r) S[nb][r] = 0.f;

        #pragma unroll 4
        for (int ks = 0; ks < 16; ++ks) {
            int k = ks * 8;
            uint32_t a[4];
            a[0] = __float_as_uint(As[r0 + g][k + t]);
            a[1] = __float_as_uint(As[r0 + g + 8][k + t]);
            a[2] = __float_as_uint(As[r0 + g][k + t + 4]);
            a[3] = __float_as_uint(As[r0 + g + 8][k + t + 4]);
            uint32_t b[4][2];
            #pragma unroll
            for (int nb = 0; nb < 4; ++nb) {
                int n0 = warpN * 32 + nb * 8;
                b[nb][0] = __float_as_uint(Bs[n0 + g][k + t]);
                b[nb][1] = __float_as_uint(Bs[n0 + g][k + t + 4]);
            }
            #pragma unroll
            for (int nb = 0; nb < 4; ++nb)
                mma8(S[nb], a, b[nb]);
        }

        // epilogue: mask + |S| accumulation + store S (tf32) into Ss
        bool diag = (kt == qt);
        #pragma unroll
        for (int nb = 0; nb < 4; ++nb) {
            int col = warpN * 32 + nb * 8 + 2 * t;
            #pragma unroll
            for (int rh = 0; rh < 2; ++rh) {
                int row = r0 + g + rh * 8;
                float v0 = S[nb][rh * 2 + 0];
                float v1 = S[nb][rh * 2 + 1];
                if (diag) {
                    if (col + 0 > row) v0 = 0.f;
                    if (col + 1 > row) v1 = 0.f;
                }
                asum[rh] += fabsf(v0) + fabsf(v1);
                float2 st;
                st.x = __uint_as_float(f2tf(v0));
                st.y = __uint_as_float(f2tf(v1));
                *(float2*)&Ss[row][col] = st;
            }
        }
        __syncthreads();   // Ss complete (all warps) before mma2 reads cross-warp cols

        // mma2: O(16x32 per warp) += S(64 keys) · Vt^T
        #pragma unroll 4
        for (int ks = 0; ks < 8; ++ks) {
            int k = ks * 8;
            uint32_t a[4];
            a[0] = __float_as_uint(Ss[r0 + g][k + t]);
            a[1] = __float_as_uint(Ss[r0 + g + 8][k + t]);
            a[2] = __float_as_uint(Ss[r0 + g][k + t + 4]);
            a[3] = __float_as_uint(Ss[r0 + g + 8][k + t + 4]);
            uint32_t b[4][2];
            #pragma unroll
            for (int nb = 0; nb < 4; ++nb) {
                int n0 = warpN * 32 + nb * 8;
                b[nb][0] = __float_as_uint(Vs[n0 + g][k + t]);
                b[nb][1] = __float_as_uint(Vs[n0 + g][k + t + 4]);
            }
            #pragma unroll
            for (int nb = 0; nb < 4; ++nb)
                mma8(O[nb], a, b[nb]);
        }
    }

    __syncthreads();
    // per-row |S| sum: 8 partials per row -> reduce
    asums[r0 + g][warpN * 4 + t]     = asum[0];
    asums[r0 + g + 8][warpN * 4 + t] = asum[1];
    __syncthreads();
    if (tid < 64) {
        float s = 0.f;
        #pragma unroll
        for (int j = 0; j < 8; ++j) s += asums[tid][j];
        asums[tid][0] = 1.f / s;
    }
    __syncthreads();

    #pragma unroll
    for (int rh = 0; rh < 2; ++rh) {
        int row = r0 + g + rh * 8;
        float inv = asums[row][0];
        int l = q0 + row;
        float* op = out + ((size_t)(n * SEQL + l)) * DMODEL + h * HDIM;
        #pragma unroll
        for (int nb = 0; nb < 4; ++nb) {
            int col = warpN * 32 + nb * 8 + 2 * t;
            float2 st;
            st.x = O[nb][rh * 2 + 0] * inv;
            st.y = O[nb][rh * 2 + 1] * inv;
            *(float2*)(op + col) = st;
        }
    }
}

// ─────────────────────────── launch ─────────────────────────────────────────
extern "C" void kernel_launch(void* const* d_in, const int* in_sizes, int n_in,
                              void* d_out, int out_size)
{
    const float* query = (const float*)d_in[0];
    const float* key   = (const float*)d_in[1];
    const float* Wq    = (const float*)d_in[2];
    const float* Wk    = (const float*)d_in[3];
    const float* Wv    = (const float*)d_in[4];
    const float* coeff = (const float*)d_in[5];
    const float* pw    = (const float*)d_in[6];
    const float* pb    = (const float*)d_in[7];
    float* out = (float*)d_out;

    cudaFuncSetAttribute(proj_tc, cudaFuncAttributeMaxDynamicSharedMemorySize, PJ_SMEM);
    cudaFuncSetAttribute(attn_tc, cudaFuncAttributeMaxDynamicSharedMemorySize, AT_SMEM);

    proj_tc<<<dim3(32, 4, 3), 256, PJ_SMEM>>>(query, key, Wq, Wk, Wv, coeff, pw, pb);
    attn_tc<<<dim3(32, 16), 256, AT_SMEM>>>(out);
}

// round 7
// speedup vs baseline: 1.1638x; 1.1638x over previous
#include <cuda_runtime.h>
#include <math.h>
#include <cstdint>

#define SEQL   2048
#define NHEAD  8
#define DMODEL 512
#define HDIM   64
#define CATD   128
#define NHTOT  16

// Scratch (allocation-free). Values stored pre-rounded to tf32 bit patterns.
__device__ float g_A [(size_t)NHTOT * SEQL * CATD];   // [nh][l][c]   A operand (K-major)
__device__ float g_B [(size_t)NHTOT * SEQL * CATD];   // [nh][l][c]   B operand (K-major)
__device__ float g_Vt[(size_t)NHTOT * HDIM * SEQL];   // [nh][d][l]   stage-2 B operand (K-major)

#define DINL __device__ __forceinline__

DINL uint32_t f2tf(float f) {           // round fp32 -> tf32 (rna), fp32 bit layout
    uint32_t u;
    asm("cvt.rna.tf32.f32 %0, %1;" : "=r"(u) : "f"(f));
    return u;
}

// m16n8k8 tf32 MMA, fp32 accumulate (legacy mma.sync path, base sm_103 ISA)
DINL void mma8(float* d, const uint32_t* a, const uint32_t* b) {
    asm volatile("mma.sync.aligned.m16n8k8.row.col.f32.tf32.tf32.f32 "
        "{%0,%1,%2,%3}, {%4,%5,%6,%7}, {%8,%9}, {%0,%1,%2,%3};"
        : "+f"(d[0]), "+f"(d[1]), "+f"(d[2]), "+f"(d[3])
        : "r"(a[0]), "r"(a[1]), "r"(a[2]), "r"(a[3]), "r"(b[0]), "r"(b[1]));
}

DINL uint32_t smem_u32(const void* p) {
    uint32_t a;
    asm("{ .reg .u64 t; cvta.to.shared.u64 t, %1; cvt.u32.u64 %0, t; }" : "=r"(a) : "l"(p));
    return a;
}
DINL void cp16(uint32_t dst, const void* src) {
    asm volatile("cp.async.cg.shared.global [%0], [%1], 16;" :: "r"(dst), "l"(src));
}
#define CP_COMMIT_WAIT0() \
    asm volatile("cp.async.commit_group;\n\tcp.async.wait_group 0;" ::: "memory")

DINL float softplus_f(float x) {
    return fmaxf(x, 0.f) + log1pf(__expf(-fabsf(x)));
}
DINL void sincos_red(float ang, float* s, float* c) {
    const float INV2PI = 0.15915494309189535f;
    const float PI2_HI = 6.28318548202514648f;
    const float PI2_LO = -1.74845553e-7f;
    float k = rintf(ang * INV2PI);
    float r = fmaf(-k, PI2_HI, ang);
    r = fmaf(-k, PI2_LO, r);
    *s = __sinf(r);
    *c = __cosf(r);
}

// ─────────────────────────── Projection GEMM (tf32 mma.sync) ────────────────
// Unchanged from R5 (known-good numerics/perf). C(128x128) = X·W^T over K=512,
// slabs of 64 (69.6KB smem -> 2 CTAs/SM). 8 warps: 4(M) x 2(N), warp tile 32x64.
#define PJ_PITCH 68
#define PJ_SMEM  (2 * 128 * PJ_PITCH * 4)

__global__ __launch_bounds__(256, 2) void proj_tc(
    const float* __restrict__ query, const float* __restrict__ key,
    const float* __restrict__ Wq, const float* __restrict__ Wk, const float* __restrict__ Wv,
    const float* __restrict__ coeff, const float* __restrict__ pw, const float* __restrict__ pb)
{
    extern __shared__ float sm[];
    float (*Xs)[PJ_PITCH] = (float(*)[PJ_PITCH])sm;
    float (*Ws)[PJ_PITCH] = (float(*)[PJ_PITCH])(sm + 128 * PJ_PITCH);

    int tid = threadIdx.x, wid = tid >> 5, lane = tid & 31;
    int warpM = wid >> 1, warpN = wid & 1;
    int g = lane >> 2, t = lane & 3;
    int mode = blockIdx.z;
    const float* X = (mode == 0) ? query : key;
    const float* W = (mode == 0) ? Wq : (mode == 1 ? Wk : Wv);
    int m0 = blockIdx.x * 128;
    int c0 = blockIdx.y * 128;

    float acc[2][8][4];
    #pragma unroll
    for (int mb = 0; mb < 2; ++mb)
        #pragma unroll
        for (int nb = 0; nb < 8; ++nb)
            #pragma unroll
            for (int r = 0; r < 4; ++r) acc[mb][nb][r] = 0.f;

    for (int kc = 0; kc < 8; ++kc) {
        __syncthreads();
        #pragma unroll
        for (int it = 0; it < 8; ++it) {
            int idx = it * 256 + tid;
            int r = idx >> 4, c4 = (idx & 15) * 4;
            float4 vx = *(const float4*)(X + (size_t)(m0 + r) * DMODEL + kc * 64 + c4);
            Xs[r][c4 + 0] = __uint_as_float(f2tf(vx.x));
            Xs[r][c4 + 1] = __uint_as_float(f2tf(vx.y));
            Xs[r][c4 + 2] = __uint_as_float(f2tf(vx.z));
            Xs[r][c4 + 3] = __uint_as_float(f2tf(vx.w));
            float4 vw = *(const float4*)(W + (size_t)(c0 + r) * DMODEL + kc * 64 + c4);
            Ws[r][c4 + 0] = __uint_as_float(f2tf(vw.x));
            Ws[r][c4 + 1] = __uint_as_float(f2tf(vw.y));
            Ws[r][c4 + 2] = __uint_as_float(f2tf(vw.z));
            Ws[r][c4 + 3] = __uint_as_float(f2tf(vw.w));
        }
        __syncthreads();

        #pragma unroll
        for (int ks = 0; ks < 8; ++ks) {
            int k = ks * 8;
            uint32_t a[2][4];
            #pragma unroll
            for (int mb = 0; mb < 2; ++mb) {
                int r0 = warpM * 32 + mb * 16;
                a[mb][0] = __float_as_uint(Xs[r0 + g][k + t]);
                a[mb][1] = __float_as_uint(Xs[r0 + g + 8][k + t]);
                a[mb][2] = __float_as_uint(Xs[r0 + g][k + t + 4]);
                a[mb][3] = __float_as_uint(Xs[r0 + g + 8][k + t + 4]);
            }
            uint32_t b[8][2];
            #pragma unroll
            for (int nb = 0; nb < 8; ++nb) {
                int n0 = warpN * 64 + nb * 8;
                b[nb][0] = __float_as_uint(Ws[n0 + g][k + t]);
                b[nb][1] = __float_as_uint(Ws[n0 + g][k + t + 4]);
            }
            #pragma unroll
            for (int mb = 0; mb < 2; ++mb)
                #pragma unroll
                for (int nb = 0; nb < 8; ++nb)
                    mma8(acc[mb][nb], a[mb], b[nb]);
        }
    }

    // epilogue
    #pragma unroll
    for (int mb = 0; mb < 2; ++mb) {
        #pragma unroll
        for (int nb = 0; nb < 8; ++nb) {
            #pragma unroll
            for (int r = 0; r < 4; ++r) {
                int row = warpM * 32 + mb * 16 + g + (r >> 1) * 8;
                int col = warpN * 64 + nb * 8 + 2 * t + (r & 1);
                int m = m0 + row;
                int n = m >> 11, l = m & (SEQL - 1);
                int c = c0 + col;
                int h = c >> 6, dd = c & 63;
                float x = acc[mb][nb][r];
                if (mode == 2) {
                    g_Vt[((size_t)((n * NHEAD + h) * HDIM + dd)) * SEQL + l] =
                        __uint_as_float(f2tf(x));
                } else {
                    size_t base = ((size_t)(n * NHEAD + h) * SEQL + l) * CATD;
                    float w = pw[c];
                    float sn, cs;
                    if (mode == 0) {
                        float sp = softplus_f(x);
                        sincos_red((float)l * w + pb[c], &sn, &cs);
                        g_A[base + dd]      = __uint_as_float(f2tf(sp * cs));
                        g_A[base + 64 + dd] = __uint_as_float(f2tf(sp * sn));
                    } else {
                        float sp = softplus_f(x) * coeff[c];
                        sincos_red((float)l * w, &sn, &cs);
                        g_B[base + dd]      = __uint_as_float(f2tf(sp * cs));
                        g_B[base + 64 + dd] = __uint_as_float(f2tf(sp * sn));
                    }
                }
            }
        }
    }
}

// ─────────────────────────── Attention (tf32 mma.sync, causal, abs-norm) ────
// 128 threads, 4 warps. CTA = (nh, 64 q rows); warp w owns rows [16w,16w+16)
// and ALL 64 keys of each chunk (warp tile 16x64):
//   - A-fragments (q side) loaded ONCE into 64 registers (reused every chunk)
//   - mma1: S(16x64) = A · B^T  (b-frags from Bs, scalar conflict-free LDS)
//   - epilogue: causal mask, asum += |S| (regs), S -> warp-PRIVATE smem (syncwarp only)
//   - mma2: O(16x64) += S · Vt^T
// Staging via cp.async (data pre-rounded tf32 -> raw copy). 67KB smem -> 3 CTAs/SM.
#define AP 132            // Bs pitch (4g+t bank pattern -> conflict-free scalar LDS)
#define VP 68
#define SP 68
#define AT_BS_F   0
#define AT_VS_F   (64 * AP)                 // 8448
#define AT_SS_F   (64 * AP + 64 * VP)       // 12800
#define AT_SMEM   ((64 * AP + 64 * VP + 4 * 16 * SP) * 4)   // 68608 bytes

__global__ __launch_bounds__(128, 3) void attn_tc(float* __restrict__ out)
{
    extern __shared__ float sm[];
    float (*Bs)[AP] = (float(*)[AP])(sm + AT_BS_F);
    float (*Vs)[VP] = (float(*)[VP])(sm + AT_VS_F);

    int tid = threadIdx.x, wid = tid >> 5, lane = tid & 31;
    int g = lane >> 2, t = lane & 3;
    int wr = wid * 16;                                  // warp's q-row base (local)
    float (*Ssw)[SP] = (float(*)[SP])(sm + AT_SS_F + wid * 16 * SP);  // warp-private

    int nh = blockIdx.y;
    int n = nh >> 3, h = nh & 7;
    int qt = (int)gridDim.x - 1 - (int)blockIdx.x;      // heavy tiles first
    int q0 = qt * 64;

    const float* Ab = g_A  + (size_t)nh * SEQL * CATD;
    const float* Bb = g_B  + (size_t)nh * SEQL * CATD;
    const float* Vb = g_Vt + (size_t)nh * HDIM * SEQL;

    uint32_t bs_u = smem_u32(sm);

    // ── one-time: stage A tile (64x128) into Bs region, pull a-frags to regs ──
    #pragma unroll
    for (int it = 0; it < 16; ++it) {
        int idx = it * 128 + tid;
        int r = idx >> 5, c4 = (idx & 31) * 4;
        cp16(bs_u + (uint32_t)(r * AP + c4) * 4, Ab + (size_t)(q0 + r) * CATD + c4);
    }
    CP_COMMIT_WAIT0();
    __syncthreads();

    uint32_t a[16][4];
    #pragma unroll
    for (int ks = 0; ks < 16; ++ks) {
        int k = ks * 8;
        a[ks][0] = __float_as_uint(Bs[wr + g][k + t]);
        a[ks][1] = __float_as_uint(Bs[wr + g + 8][k + t]);
        a[ks][2] = __float_as_uint(Bs[wr + g][k + t + 4]);
        a[ks][3] = __float_as_uint(Bs[wr + g + 8][k + t + 4]);
    }

    float O[8][4];
    #pragma unroll
    for (int nb = 0; nb < 8; ++nb)
        #pragma unroll
        for (int r = 0; r < 4; ++r) O[nb][r] = 0.f;
    float asum[2] = {0.f, 0.f};

    for (int kt = 0; kt <= qt; ++kt) {
        int k0 = kt * 64;
        __syncthreads();   // prior mma1/mma2 (and a-frag pulls, iter 0) done with Bs/Vs

        // ── stage B chunk (64x128) + V chunk (64x64) via cp.async ──
        #pragma unroll
        for (int it = 0; it < 16; ++it) {
            int idx = it * 128 + tid;
            int r = idx >> 5, c4 = (idx & 31) * 4;
            cp16(bs_u + (uint32_t)(r * AP + c4) * 4, Bb + (size_t)(k0 + r) * CATD + c4);
        }
        #pragma unroll
        for (int it = 0; it < 8; ++it) {
            int idx = it * 128 + tid;
            int r = idx >> 4, c4 = (idx & 15) * 4;
            cp16(bs_u + (uint32_t)(AT_VS_F + r * VP + c4) * 4,
                 Vb + (size_t)r * SEQL + k0 + c4);
        }
        CP_COMMIT_WAIT0();
        __syncthreads();

        // ── mma1: S(16x64) = A · B^T over catd=128 (a-frags from registers) ──
        float S[8][4];
        #pragma unroll
        for (int nb = 0; nb < 8; ++nb)
            #pragma unroll
            for (int r = 0; r < 4; ++r) S[nb][r] = 0.f;

        #pragma unroll 4
        for (int ks = 0; ks < 16; ++ks) {
            int k = ks * 8;
            uint32_t b[8][2];
            #pragma unroll
            for (int nb = 0; nb < 8; ++nb) {
                int n0 = nb * 8;
                b[nb][0] = __float_as_uint(Bs[n0 + g][k + t]);
                b[nb][1] = __float_as_uint(Bs[n0 + g][k + t + 4]);
            }
            #pragma unroll
            for (int nb = 0; nb < 8; ++nb)
                mma8(S[nb], a[ks], b[nb]);
        }

        // ── epilogue: mask + |S| accumulation + S (tf32) into warp-private Ssw ──
        bool diag = (kt == qt);
        #pragma unroll
        for (int nb = 0; nb < 8; ++nb) {
            int col = nb * 8 + 2 * t;                   // local key col
            #pragma unroll
            for (int rh = 0; rh < 2; ++rh) {
                int rowl = g + rh * 8;                  // local row within warp tile
                float v0 = S[nb][rh * 2 + 0];
                float v1 = S[nb][rh * 2 + 1];
                if (diag) {
                    int qg = wr + rowl;                 // local q (k0 == q0 base)
                    if (col + 0 > qg) v0 = 0.f;
                    if (col + 1 > qg) v1 = 0.f;
                }
                asum[rh] += fabsf(v0) + fabsf(v1);
                float2 st;
                st.x = __uint_as_float(f2tf(v0));
                st.y = __uint_as_float(f2tf(v1));
                *(float2*)&Ssw[rowl][col] = st;
            }
        }
        __syncwarp();                                   // warp-private Ssw -> no CTA barrier

        // ── mma2: O(16x64) += S · Vt^T over 64 keys ──
        #pragma unroll 4
        for (int ks = 0; ks < 8; ++ks) {
            int k = ks * 8;
            uint32_t a2[4];
            a2[0] = __float_as_uint(Ssw[g][k + t]);
            a2[1] = __float_as_uint(Ssw[g + 8][k + t]);
            a2[2] = __float_as_uint(Ssw[g][k + t + 4]);
            a2[3] = __float_as_uint(Ssw[g + 8][k + t + 4]);
            uint32_t b[8][2];
            #pragma unroll
            for (int nb = 0; nb < 8; ++nb) {
                int n0 = nb * 8;
                b[nb][0] = __float_as_uint(Vs[n0 + g][k + t]);
                b[nb][1] = __float_as_uint(Vs[n0 + g][k + t + 4]);
            }
            #pragma unroll
            for (int nb = 0; nb < 8; ++nb)
                mma8(O[nb], a2, b[nb]);
        }
    }

    // ── row |S|-sum reduction within quad (lanes share rows across t) ──
    #pragma unroll
    for (int rh = 0; rh < 2; ++rh) {
        asum[rh] += __shfl_xor_sync(0xffffffffu, asum[rh], 1);
        asum[rh] += __shfl_xor_sync(0xffffffffu, asum[rh], 2);
    }

    #pragma unroll
    for (int rh = 0; rh < 2; ++rh) {
        float inv = 1.f / asum[rh];
        int l = q0 + wr + g + rh * 8;
        float* op = out + ((size_t)(n * SEQL + l)) * DMODEL + h * HDIM;
        #pragma unroll
        for (int nb = 0; nb < 8; ++nb) {
            int col = nb * 8 + 2 * t;
            float2 st;
            st.x = O[nb][rh * 2 + 0] * inv;
            st.y = O[nb][rh * 2 + 1] * inv;
            *(float2*)(op + col) = st;
        }
    }
}

// ─────────────────────────── launch ─────────────────────────────────────────
extern "C" void kernel_launch(void* const* d_in, const int* in_sizes, int n_in,
                              void* d_out, int out_size)
{
    const float* query = (const float*)d_in[0];
    const float* key   = (const float*)d_in[1];
    const float* Wq    = (const float*)d_in[2];
    const float* Wk    = (const float*)d_in[3];
    const float* Wv    = (const float*)d_in[4];
    const float* coeff = (const float*)d_in[5];
    const float* pw    = (const float*)d_in[6];
    const float* pb    = (const float*)d_in[7];
    float* out = (float*)d_out;

    cudaFuncSetAttribute(proj_tc, cudaFuncAttributeMaxDynamicSharedMemorySize, PJ_SMEM);
    cudaFuncSetAttribute(attn_tc, cudaFuncAttributeMaxDynamicSharedMemorySize, AT_SMEM);

    proj_tc<<<dim3(32, 4, 3), 256, PJ_SMEM>>>(query, key, Wq, Wk, Wv, coeff, pw, pb);
    attn_tc<<<dim3(32, 16), 128, AT_SMEM>>>(out);
}